// round 7
// baseline (speedup 1.0000x reference)
#include <cuda_runtime.h>
#include <cuda_fp16.h>
#include <cstdint>

#define HID      512
#define NOBJ     8192
#define NREL     32768
#define POOL     4096
#define NRELCLS  51
#define NOBJCLS  151

// -------------------- device scratch --------------------
__device__ __align__(256) __half g_edge_hi[NOBJ * 1024];
__device__ __align__(256) __half g_wcatT[POOL * 1024];   // [n][k] fp16
__device__ __align__(256) __half g_wctxT[64 * POOL];     // [cls pad64][k] fp16
__device__ __align__(256) __half g_ec_hi[NOBJ * HID];    // edge_ctx split
__device__ __align__(256) __half g_ec_lo[NOBJ * HID];
__device__ __align__(256) __half g_wembT[1024 * HID];    // [n][k] fp16

// -------------------- helpers --------------------
__device__ __forceinline__ uint32_t smem_u32(const void* p) {
    uint32_t a;
    asm("{ .reg .u64 t; cvta.to.shared.u64 t, %1; cvt.u32.u64 %0, t; }" : "=r"(a) : "l"(p));
    return a;
}
#define CP16(d, s)   asm volatile("cp.async.cg.shared.global [%0], [%1], 16;" :: "r"(d), "l"(s) : "memory")
#define CP_COMMIT()  asm volatile("cp.async.commit_group;" ::: "memory")
#define WAITG(n)     asm volatile("cp.async.wait_group %0;" :: "n"(n) : "memory")

__device__ __forceinline__ void ldsm4(uint32_t* r, uint32_t a) {
    asm volatile("ldmatrix.sync.aligned.m8n8.x4.shared.b16 {%0,%1,%2,%3}, [%4];"
                 : "=r"(r[0]), "=r"(r[1]), "=r"(r[2]), "=r"(r[3]) : "r"(a));
}
__device__ __forceinline__ void mma16816(float* d, const uint32_t* a, uint32_t b0, uint32_t b1) {
    asm volatile(
        "mma.sync.aligned.m16n8k16.row.col.f32.f16.f16.f32 "
        "{%0,%1,%2,%3}, {%4,%5,%6,%7}, {%8,%9}, {%0,%1,%2,%3};"
        : "+f"(d[0]), "+f"(d[1]), "+f"(d[2]), "+f"(d[3])
        : "r"(a[0]), "r"(a[1]), "r"(a[2]), "r"(a[3]), "r"(b0), "r"(b1));
}
__device__ __forceinline__ uint32_t packh(float e0, float e1) {
    uint32_t r;
    asm("cvt.rn.f16x2.f32 %0, %1, %2;" : "=r"(r) : "f"(e1), "f"(e0));  // low = e0
    return r;
}

// -------------------- smem layout: fused kernel (bytes) --------------------
#define STAGE    32768           // A [128m][64k] 16KB + B [128n][64k] 16KB
#define OFF_A    0
#define OFF_B    16384
#define ZOFF     65536           // z [128m][64k] fp16 (one k-half)  16KB
#define WCOFF    81920           // 2 subs of Wctx [64cls][64k]      16KB
#define P0OFF    98304
#define P1OFF    98816
#define OPOFF    99328
#define SMEM_FUSED 99840         // 97.5 KB -> 2 CTAs/SM

// -------------------- smem layout: gemm1 kernel --------------------
#define G1STAGE  49152
#define G1_AHI   0
#define G1_ALO   16384
#define G1_B     32768
#define SMEM_G1  98304

// ===========================================================================
// Preps
// ===========================================================================
__global__ void k_ec_prep(const float* __restrict__ src) {
    int idx = blockIdx.x * 256 + threadIdx.x;
    float v = src[idx];
    __half h = __float2half_rn(v);
    g_ec_hi[idx] = h;
    g_ec_lo[idx] = __float2half_rn(v - __half2float(h));
}

__global__ void k_wemb_prep(const float* __restrict__ src) {  // [512][1024] -> [1024][512]
    __shared__ float tile[32][33];
    int tx = threadIdx.x, ty = threadIdx.y;
    int c0 = blockIdx.x * 32, r0 = blockIdx.y * 32;
    for (int i = ty; i < 32; i += 8)
        tile[i][tx] = src[(size_t)(r0 + i) * 1024 + c0 + tx];
    __syncthreads();
    for (int i = ty; i < 32; i += 8)
        g_wembT[(size_t)(c0 + i) * HID + r0 + tx] = __float2half_rn(tile[tx][i]);
}

__global__ void k_wcat_prep(const float* __restrict__ src) {  // [1024][4096] -> [4096][1024]
    __shared__ float tile[32][33];
    int tx = threadIdx.x, ty = threadIdx.y;
    int c0 = blockIdx.x * 32, r0 = blockIdx.y * 32;
    for (int i = ty; i < 32; i += 8)
        tile[i][tx] = src[(size_t)(r0 + i) * POOL + c0 + tx];
    __syncthreads();
    for (int i = ty; i < 32; i += 8)
        g_wcatT[(size_t)(c0 + i) * 1024 + r0 + tx] = __float2half_rn(tile[tx][i]);
}

__global__ void k_wctx_prep(const float* __restrict__ Wctx) {
    int idx = blockIdx.x * 256 + threadIdx.x;   // 64*4096
    int c = idx >> 12, k = idx & 4095;
    float v = (c < NRELCLS) ? Wctx[(size_t)k * NRELCLS + c] : 0.f;
    g_wctxT[idx] = __float2half_rn(v);
}

// ===========================================================================
// GEMM1 (mma, 2-pass A): edge_rep = relu(edge_ctx @ W_post_emb + b) -> fp16
// ===========================================================================
__global__ __launch_bounds__(512, 1) void k_gemm1_mma(const float* __restrict__ bias)
{
    extern __shared__ __align__(1024) char smc[];
    const uint32_t sb = smem_u32(smc);
    const int t = threadIdx.x;
    const int lane = t & 31, wid = t >> 5;
    const int wm = wid >> 2, wn = wid & 3;
    const int m0 = blockIdx.x * 128, n0 = blockIdx.y * 128;

    auto load_stage = [&](int kc) {
        const uint32_t base = sb + (kc & 1) * G1STAGE;
#pragma unroll
        for (int i = 0; i < 2; i++) {
            int idx = t + i * 512;
            int row = idx >> 3, j = idx & 7;
            uint32_t d = (uint32_t)row * 128 + (((uint32_t)j * 16) ^ ((uint32_t)(row & 7) << 4));
            CP16(base + G1_AHI + d, &g_ec_hi[(size_t)(m0 + row) * HID + kc * 64 + j * 8]);
            CP16(base + G1_ALO + d, &g_ec_lo[(size_t)(m0 + row) * HID + kc * 64 + j * 8]);
            CP16(base + G1_B   + d, &g_wembT[(size_t)(n0 + row) * HID + kc * 64 + j * 8]);
        }
    };
    load_stage(0); CP_COMMIT();
    load_stage(1); CP_COMMIT();

    const uint32_t xorv = (lane & 7) << 4;
    const uint32_t khb  = (lane >> 4) * 16;
    const uint32_t arow = (uint32_t)(wm * 32 + (lane & 15)) * 128;
    const uint32_t brow = (uint32_t)(wn * 32 + (lane & 15)) * 128;

    float acc[2][4][4];
#pragma unroll
    for (int a = 0; a < 2; a++)
#pragma unroll
        for (int b = 0; b < 4; b++)
#pragma unroll
            for (int c = 0; c < 4; c++) acc[a][b][c] = 0.f;

    for (int kc = 0; kc < 8; kc++) {
        if (kc == 7) { WAITG(0); } else { WAITG(1); }
        __syncthreads();
        const uint32_t base = sb + (kc & 1) * G1STAGE;
#pragma unroll
        for (int ks = 0; ks < 4; ks++) {
            const uint32_t col = (uint32_t)(ks * 32 + khb) ^ xorv;
            uint32_t bf[2][4];
            ldsm4(bf[0], base + G1_B + brow + col);
            ldsm4(bf[1], base + G1_B + brow + 16 * 128 + col);
            uint32_t ah[2][4], al[2][4];
#pragma unroll
            for (int mt = 0; mt < 2; mt++) {
                ldsm4(ah[mt], base + G1_AHI + arow + mt * 16 * 128 + col);
                ldsm4(al[mt], base + G1_ALO + arow + mt * 16 * 128 + col);
            }
#pragma unroll
            for (int mt = 0; mt < 2; mt++)
#pragma unroll
                for (int nt = 0; nt < 4; nt++) {
                    uint32_t b0 = bf[nt >> 1][nt & 1], b1 = bf[nt >> 1][2 + (nt & 1)];
                    mma16816(acc[mt][nt], ah[mt], b0, b1);
                    mma16816(acc[mt][nt], al[mt], b0, b1);
                }
        }
        __syncthreads();
        if (kc + 2 < 8) { load_stage(kc + 2); CP_COMMIT(); }
    }

#pragma unroll
    for (int mt = 0; mt < 2; mt++) {
        const int row = m0 + wm * 32 + mt * 16 + (lane >> 2);
#pragma unroll
        for (int nt = 0; nt < 4; nt++) {
            const int col = n0 + wn * 32 + nt * 8 + (lane & 3) * 2;
            float2 bb = *(const float2*)&bias[col];
            __half2 h0 = __floats2half2_rn(fmaxf(acc[mt][nt][0] + bb.x, 0.f),
                                           fmaxf(acc[mt][nt][1] + bb.y, 0.f));
            __half2 h1 = __floats2half2_rn(fmaxf(acc[mt][nt][2] + bb.x, 0.f),
                                           fmaxf(acc[mt][nt][3] + bb.y, 0.f));
            *(__half2*)&g_edge_hi[(size_t)row * 1024 + col] = h0;
            *(__half2*)&g_edge_hi[(size_t)(row + 8) * 1024 + col] = h1;
        }
    }
}

// ===========================================================================
// Fused: GEMM2 -> *union -> GEMM3 -> +freq
// 128 threads (4 warps), 2 CTAs/SM. CTA tile M128 x N128, warp tile 64x64.
// k-stage 64, 2-stage cp.async. 32 pool chunks of 128; GEMM3 in 2 k-halves.
// ===========================================================================
__global__ __launch_bounds__(128, 2) void k_fused_mma(
    const float* __restrict__ bcat,
    const float* __restrict__ unionf,
    const int*   __restrict__ pairs,
    const int*   __restrict__ obj_preds,
    const float* __restrict__ bctx,
    const float* __restrict__ freq,
    float*       __restrict__ out)
{
    extern __shared__ __align__(1024) char smc[];
    const uint32_t sb = smem_u32(smc);
    const int t = threadIdx.x;
    const int lane = t & 31, wid = t >> 5;
    const int wm = wid >> 1, wn = wid & 1;   // GEMM2: 2m x 2n, warp tile 64x64
    const int r0 = blockIdx.x * 128;

    int* p0s = (int*)(smc + P0OFF);
    int* p1s = (int*)(smc + P1OFF);
    int* opx = (int*)(smc + OPOFF);

    {
        int a = pairs[(size_t)(r0 + t) * 2 + 0];
        int b = pairs[(size_t)(r0 + t) * 2 + 1];
        p0s[t] = a; p1s[t] = b;
        opx[t] = obj_preds[a] * NOBJCLS + obj_preds[b];
    }
    __syncthreads();

    // stage loader: A [128m][64k] gathered + B [128n][64k]; g = nc*16 + kst (512)
    auto load_stage = [&](int g) {
        const int st = g & 1, kc = g & 15, ncn = g >> 4;
        const uint32_t base = sb + st * STAGE;
#pragma unroll
        for (int i = 0; i < 8; i++) {           // A: 1024 slots
            int idx = t + i * 128;
            int row = idx >> 3, j = idx & 7;
            uint32_t d = (uint32_t)row * 128 + (((uint32_t)j * 16) ^ ((uint32_t)(row & 7) << 4));
            int src = (kc < 8) ? p0s[row] : p1s[row];
            CP16(base + OFF_A + d, &g_edge_hi[(size_t)src * 1024 + kc * 64 + j * 8]);
        }
#pragma unroll
        for (int i = 0; i < 8; i++) {           // B: 1024 slots
            int idx = t + i * 128;
            int row = idx >> 3, j = idx & 7;
            uint32_t d = (uint32_t)row * 128 + (((uint32_t)j * 16) ^ ((uint32_t)(row & 7) << 4));
            CP16(base + OFF_B + d, &g_wcatT[((size_t)(ncn * 128 + row)) * 1024 + kc * 64 + j * 8]);
        }
    };

    load_stage(0); CP_COMMIT();
    load_stage(1); CP_COMMIT();

    const uint32_t xorv = (lane & 7) << 4;
    const uint32_t khb  = (lane >> 4) * 16;
    const uint32_t arow = (uint32_t)(wm * 64 + (lane & 15)) * 128;
    const uint32_t brow = (uint32_t)(wn * 64 + (lane & 15)) * 128;
    const uint32_t zrow = (uint32_t)(wid * 32 + (lane & 15)) * 128;  // GEMM3: warp=32 rows
    const uint32_t wrow = (uint32_t)(lane & 15) * 128;
    const uint32_t zxor = ((lane >> 2) & 7) << 4;

    float acc3[2][8][4];
#pragma unroll
    for (int a = 0; a < 2; a++)
#pragma unroll
        for (int b = 0; b < 8; b++)
#pragma unroll
            for (int c = 0; c < 4; c++) acc3[a][b][c] = 0.f;

    for (int nc = 0; nc < 32; nc++) {
        const int n0 = nc * 128;
        float acc2[4][8][4];
#pragma unroll
        for (int a = 0; a < 4; a++)
#pragma unroll
            for (int b = 0; b < 8; b++)
#pragma unroll
                for (int c = 0; c < 4; c++) acc2[a][b][c] = 0.f;

        // ---------------- GEMM2 K loop: 16 stages of 64k ----------------
        for (int kst = 0; kst < 16; kst++) {
            const int g = nc * 16 + kst;
            if (g == 511) { WAITG(0); } else { WAITG(1); }
            __syncthreads();

            const uint32_t base = sb + (g & 1) * STAGE;
#pragma unroll
            for (int ks = 0; ks < 4; ks++) {
                const uint32_t col = (uint32_t)(ks * 32 + khb) ^ xorv;
                uint32_t bf[4][4];
#pragma unroll
                for (int q = 0; q < 4; q++)
                    ldsm4(bf[q], base + OFF_B + brow + q * 16 * 128 + col);
                uint32_t ah[4][4];
#pragma unroll
                for (int mt = 0; mt < 4; mt++)
                    ldsm4(ah[mt], base + OFF_A + arow + mt * 16 * 128 + col);
#pragma unroll
                for (int mt = 0; mt < 4; mt++)
#pragma unroll
                    for (int nt = 0; nt < 8; nt++)
                        mma16816(acc2[mt][nt], ah[mt],
                                 bf[nt >> 1][nt & 1], bf[nt >> 1][2 + (nt & 1)]);
            }
            __syncthreads();
            if (g + 2 < 512) { load_stage(g + 2); CP_COMMIT(); }
        }

        // W_ctx tiles for this chunk: 2 subs of [64cls][64k]
#pragma unroll
        for (int i = 0; i < 8; i++) {
            int idx = t + i * 128;               // 1024 slots
            int s = idx >> 9, rem = idx & 511, row = rem >> 3, j = rem & 7;
            uint32_t d = (uint32_t)(WCOFF + s * 8192) + (uint32_t)row * 128 +
                         (((uint32_t)j * 16) ^ ((uint32_t)(row & 7) << 4));
            CP16(sb + d, &g_wctxT[(size_t)row * POOL + n0 + s * 64 + j * 8]);
        }
        CP_COMMIT();

        // ---------------- epilogue + GEMM3 in 2 k-halves ----------------
#pragma unroll 1
        for (int h = 0; h < 2; h++) {
            if (wn == h) {
                // z = (acc2 + bcat) * union for this warp's 64 cols -> z tile
#pragma unroll
                for (int mt = 0; mt < 4; mt++) {
                    const int mloc = wm * 64 + mt * 16 + (lane >> 2);
#pragma unroll
                    for (int nt = 0; nt < 8; nt++) {
                        const int kl = nt * 8 + (lane & 3) * 2;          // 0..63
                        const int ng = n0 + h * 64 + kl;
                        float2 bb = *(const float2*)&bcat[ng];
                        float2 u0 = *(const float2*)&unionf[(size_t)(r0 + mloc) * POOL + ng];
                        float2 u1 = *(const float2*)&unionf[(size_t)(r0 + mloc + 8) * POOL + ng];
                        uint32_t h01 = packh((acc2[mt][nt][0] + bb.x) * u0.x,
                                             (acc2[mt][nt][1] + bb.y) * u0.y);
                        uint32_t h23 = packh((acc2[mt][nt][2] + bb.x) * u1.x,
                                             (acc2[mt][nt][3] + bb.y) * u1.y);
                        uint32_t d0 = (uint32_t)mloc * 128 + (((uint32_t)kl * 2) ^ zxor);
                        *(uint32_t*)(smc + ZOFF + d0) = h01;
                        *(uint32_t*)(smc + ZOFF + d0 + 8 * 128) = h23;
                    }
                }
            }
            if (h == 0) { WAITG(0); }   // WC tiles arrived (also drains stage prefetch)
            __syncthreads();

            // GEMM3 sub h: acc3 += z[128][64] x Wctx_sub_h[64cls][64k]
#pragma unroll
            for (int ks = 0; ks < 4; ks++) {
                const uint32_t col = (uint32_t)(ks * 32 + khb) ^ xorv;
                uint32_t bf[4][4];
#pragma unroll
                for (int q = 0; q < 4; q++)
                    ldsm4(bf[q], sb + WCOFF + h * 8192 + wrow + q * 16 * 128 + col);
                uint32_t zf[2][4];
#pragma unroll
                for (int mt = 0; mt < 2; mt++)
                    ldsm4(zf[mt], sb + ZOFF + zrow + mt * 16 * 128 + col);
#pragma unroll
                for (int mt = 0; mt < 2; mt++)
#pragma unroll
                    for (int nt = 0; nt < 8; nt++)
                        mma16816(acc3[mt][nt], zf[mt],
                                 bf[nt >> 1][nt & 1], bf[nt >> 1][2 + (nt & 1)]);
            }
            __syncthreads();   // z consumed before next half / next chunk
        }
    }

    // ---------------- final: out = acc3 + bctx + freq ----------------
#pragma unroll
    for (int mt = 0; mt < 2; mt++) {
        const int m0l = wid * 32 + mt * 16 + (lane >> 2);
#pragma unroll
        for (int r = 0; r < 2; r++) {
            const int m = m0l + r * 8;
            const int pidx = opx[m];
            const float* fr = &freq[(size_t)pidx * NRELCLS];
            float* op = &out[(size_t)(r0 + m) * NRELCLS];
#pragma unroll
            for (int nt = 0; nt < 8; nt++) {
                const int c = nt * 8 + (lane & 3) * 2;
                if (c < NRELCLS)
                    op[c] = acc3[mt][nt][r * 2 + 0] + bctx[c] + fr[c];
                if (c + 1 < NRELCLS)
                    op[c + 1] = acc3[mt][nt][r * 2 + 1] + bctx[c + 1] + fr[c + 1];
            }
        }
    }
}

// ===========================================================================
extern "C" void kernel_launch(void* const* d_in, const int* in_sizes, int n_in,
                              void* d_out, int out_size)
{
    const float* edge_ctx   = (const float*)d_in[0];
    const float* unionf     = (const float*)d_in[1];
    const int*   pairs      = (const int*)  d_in[2];
    const int*   obj_preds  = (const int*)  d_in[3];
    const float* W_post_emb = (const float*)d_in[4];
    const float* b_post_emb = (const float*)d_in[5];
    const float* W_post_cat = (const float*)d_in[6];
    const float* b_post_cat = (const float*)d_in[7];
    const float* W_ctx      = (const float*)d_in[8];
    const float* b_ctx      = (const float*)d_in[9];
    const float* freq       = (const float*)d_in[10];
    float* out = (float*)d_out;

    cudaFuncSetAttribute(k_gemm1_mma, cudaFuncAttributeMaxDynamicSharedMemorySize, SMEM_G1);
    cudaFuncSetAttribute(k_fused_mma, cudaFuncAttributeMaxDynamicSharedMemorySize, SMEM_FUSED);

    k_ec_prep<<<(NOBJ * HID) / 256, 256>>>(edge_ctx);
    k_wemb_prep<<<dim3(1024 / 32, HID / 32), dim3(32, 8)>>>(W_post_emb);
    k_wcat_prep<<<dim3(POOL / 32, 1024 / 32), dim3(32, 8)>>>(W_post_cat);
    k_wctx_prep<<<(64 * POOL) / 256, 256>>>(W_ctx);
    k_gemm1_mma<<<dim3(NOBJ / 128, 1024 / 128), 512, SMEM_G1>>>(b_post_emb);
    k_fused_mma<<<NREL / 128, 128, SMEM_FUSED>>>(b_post_cat, unionf, pairs, obj_preds,
                                                 b_ctx, freq, out);
}